// round 11
// baseline (speedup 1.0000x reference)
#include <cuda_runtime.h>
#include <cuda_bf16.h>
#include <math.h>

// SurfNetwork v10: row-pair processing (M=256 GEMM, 4 m16-tiles per warp).
// Every B-fragment (weight) load feeds 2x the M -> per-row weight-LDS halves.
// Register-resident activations (v6 scheme), software-pipelined gathers split
// across layer0/layer1. 2 blocks/SM.

#define BN   128
#define LVL  6
#define DIRD 16
#define GEO  18

#define SW0G 20
#define SW1  36
#define SW2  36
#define SAG  20
#define SCB  9

typedef unsigned int u32;

#define O_W0GT 0        // 64*20
#define O_W1T  1280     // 64*36
#define O_W2T  3584     // 8*36
#define O_W0D  3872     // 16*64 fp32
#define O_B0   4896     // 64
#define O_B1   4960     // 64
#define O_B2   5024     // 8
#define O_BASE 5032     // 2*64
#define O_SIG  5160     // 2*128
#define O_MAX  5416     // 2*4
#define O_COL  5424     // 2*12
#define O_ACTG 5448     // 256*20
#define O_COLB 10568    // 256*9
#define SMEM_WORDS 12872
#define SMEM_BYTES (SMEM_WORDS * 4)   // 51488

__device__ __forceinline__ u32 pkbf(float lo, float hi) {
    u32 r; asm("cvt.rn.bf16x2.f32 %0, %1, %2;" : "=r"(r) : "f"(hi), "f"(lo));
    return r;
}
__device__ __forceinline__ u32 pkrelu(float lo, float hi) {
    return pkbf(fmaxf(lo, 0.0f), fmaxf(hi, 0.0f));
}
__device__ __forceinline__ void mma16(float* c, const u32* a, u32 b0, u32 b1) {
    asm volatile(
        "mma.sync.aligned.m16n8k16.row.col.f32.bf16.bf16.f32 "
        "{%0,%1,%2,%3},{%4,%5,%6,%7},{%8,%9},{%0,%1,%2,%3};"
        : "+f"(c[0]), "+f"(c[1]), "+f"(c[2]), "+f"(c[3])
        : "r"(a[0]), "r"(a[1]), "r"(a[2]), "r"(a[3]), "r"(b0), "r"(b1));
}
__device__ __forceinline__ int agix(int row, int j) {
    return row * SAG + (j ^ ((row >> 3) & 3));
}

__global__ void __launch_bounds__(128, 2)
surf_pair(const int* __restrict__ x,
          const float* __restrict__ dvec,
          const float4* __restrict__ gw,
          const float* __restrict__ W0, const float* __restrict__ b0,
          const float* __restrict__ W1, const float* __restrict__ b1,
          const float* __restrict__ W2, const float* __restrict__ b2,
          float* __restrict__ outSigma, float* __restrict__ outColor,
          int B)
{
    extern __shared__ float sm[];
    u32* smu = (u32*)sm;
    const int tid  = threadIdx.x;
    const int lane = tid & 31;
    const int warp = tid >> 5;
    const int grp  = lane >> 2;
    const int tig  = lane & 3;

    // ---------- stage weights (transposed, bf16x2) ----------
    for (int i = tid; i < 64 * SW0G; i += 128) {
        int n = i / SW0G, kk = i - n * SW0G;
        u32 v = 0;
        if (kk < 16) {
            int g0 = 2 * kk, g1 = 2 * kk + 1;
            float lo = (g0 < GEO) ? W0[(DIRD + g0) * 64 + n] : 0.0f;
            float hi = (g1 < GEO) ? W0[(DIRD + g1) * 64 + n] : 0.0f;
            v = pkbf(lo, hi);
        }
        smu[O_W0GT + i] = v;
    }
    for (int i = tid; i < 64 * SW1; i += 128) {
        int n = i / SW1, kk = i - n * SW1;
        u32 v = 0;
        if (kk < 32) v = pkbf(W1[(2 * kk) * 64 + n], W1[(2 * kk + 1) * 64 + n]);
        smu[O_W1T + i] = v;
    }
    for (int i = tid; i < 8 * SW2; i += 128) {
        int n = i / SW2, kk = i - n * SW2;
        u32 v = 0;
        if (kk < 32 && n < 3) v = pkbf(W2[(2 * kk) * 3 + n], W2[(2 * kk + 1) * 3 + n]);
        smu[O_W2T + i] = v;
    }
    for (int i = tid; i < DIRD * 64; i += 128) sm[O_W0D + i] = W0[i];
    if (tid < 64) { sm[O_B0 + tid] = b0[tid]; sm[O_B1 + tid] = b1[tid]; }
    if (tid < 8)  sm[O_B2 + tid] = (tid < 3) ? b2[tid] : 0.0f;
    for (int r = tid; r < 256; r += 128)
        for (int j = 9; j < 16; j++) smu[O_ACTG + agix(r, j)] = 0;
    __syncthreads();

    const int gstride = gridDim.x;
    const int pairs = B >> 1;
    int p = blockIdx.x;
    const int s64 = tid >> 6;        // which row of the pair this thread's base serves
    const int j64 = tid & 63;

    // ---------- prologue prefetch: both rows of first pair ----------
    u32   gpk[2][9];
    float sgp[2];
    float dpre[DIRD];
    {
        #pragma unroll
        for (int s = 0; s < 2; s++) {
            const int2* xp2 = (const int2*)(x + ((size_t)(2 * p + s) * BN + tid) * LVL);
            int2 xv0 = __ldg(xp2), xv1 = __ldg(xp2 + 1), xv2 = __ldg(xp2 + 2);
            float4 f0 = __ldg(gw + xv0.x), f1 = __ldg(gw + xv0.y);
            float4 f2 = __ldg(gw + xv1.x), f3 = __ldg(gw + xv1.y);
            float4 f4v = __ldg(gw + xv2.x), f5 = __ldg(gw + xv2.y);
            sgp[s] = fminf(fmaxf(f0.x, 0.f), 1.f) * fminf(fmaxf(f1.x, 0.f), 1.f)
                   * fminf(fmaxf(f2.x, 0.f), 1.f) * fminf(fmaxf(f3.x, 0.f), 1.f)
                   * fminf(fmaxf(f4v.x, 0.f), 1.f) * fminf(fmaxf(f5.x, 0.f), 1.f);
            gpk[s][0] = pkbf(f0.y, f0.z); gpk[s][1] = pkbf(f0.w, f1.y); gpk[s][2] = pkbf(f1.z, f1.w);
            gpk[s][3] = pkbf(f2.y, f2.z); gpk[s][4] = pkbf(f2.w, f3.y); gpk[s][5] = pkbf(f3.z, f3.w);
            gpk[s][6] = pkbf(f4v.y, f4v.z); gpk[s][7] = pkbf(f4v.w, f5.y); gpk[s][8] = pkbf(f5.z, f5.w);
        }
        const float* dd = dvec + (size_t)(2 * p + s64) * DIRD;
        #pragma unroll
        for (int i = 0; i < DIRD; i++) dpre[i] = __ldg(dd + i);
    }

    while (p < pairs) {
        const int np = p + gstride;
        const bool pn = np < pairs;
        const int ra = 2 * p, rb = 2 * p + 1;

        // ============ phase 1: base, sigma pieces, ActG ============
        {
            float acc = sm[O_B0 + j64];
            #pragma unroll
            for (int i = 0; i < DIRD; i++)
                acc = fmaf(dpre[i], sm[O_W0D + i * 64 + j64], acc);
            sm[O_BASE + s64 * 64 + j64] = acc;
        }
        float sg0 = sgp[0] + 1e-4f, sg1 = sgp[1] + 1e-4f;
        sm[O_SIG + tid] = sg0;
        sm[O_SIG + 128 + tid] = sg1;
        #pragma unroll
        for (int j = 0; j < 9; j++) {
            smu[O_ACTG + agix(tid, j)]       = gpk[0][j];
            smu[O_ACTG + agix(128 + tid, j)] = gpk[1][j];
        }
        {
            float m0 = sg0, m1 = sg1;
            #pragma unroll
            for (int o = 16; o; o >>= 1) {
                m0 = fmaxf(m0, __shfl_xor_sync(0xffffffffu, m0, o));
                m1 = fmaxf(m1, __shfl_xor_sync(0xffffffffu, m1, o));
            }
            if (lane == 0) { sm[O_MAX + warp] = m0; sm[O_MAX + 4 + warp] = m1; }
        }
        __syncthreads();   // (A)
        float m0 = fmaxf(fmaxf(sm[O_MAX + 0], sm[O_MAX + 1]), fmaxf(sm[O_MAX + 2], sm[O_MAX + 3]));
        float m1 = fmaxf(fmaxf(sm[O_MAX + 4], sm[O_MAX + 5]), fmaxf(sm[O_MAX + 6], sm[O_MAX + 7]));

        float sig0 = sg0 / m0, sig1 = sg1 / m1;
        outSigma[(size_t)ra * BN + tid] = sig0;
        outSigma[(size_t)rb * BN + tid] = sig1;
        float tb0 = tid ? 1.0f - sm[O_SIG + tid - 1] / m0 : 1.0f;
        float tb1 = tid ? 1.0f - sm[O_SIG + 128 + tid - 1] / m1 : 1.0f;
        float cw0 = tb0 * sig0, cw1 = tb1 * sig1;

        // ---- prefetch stage 1: next pair's x + d ----
        int2 xva[3], xvb[3];
        if (pn) {
            const int2* xpa = (const int2*)(x + ((size_t)(2 * np) * BN + tid) * LVL);
            xva[0] = __ldg(xpa); xva[1] = __ldg(xpa + 1); xva[2] = __ldg(xpa + 2);
            const int2* xpb = (const int2*)(x + ((size_t)(2 * np + 1) * BN + tid) * LVL);
            xvb[0] = __ldg(xpb); xvb[1] = __ldg(xpb + 1); xvb[2] = __ldg(xpb + 2);
            const float* dd = dvec + (size_t)(2 * np + s64) * DIRD;
            #pragma unroll
            for (int i = 0; i < DIRD; i++) dpre[i] = __ldg(dd + i);
        }

        // m-tile act-row bases: mt 0,1 -> pair-row a; mt 2,3 -> pair-row b
        int mrow[4];
        #pragma unroll
        for (int mt = 0; mt < 4; mt++)
            mrow[mt] = ((mt >> 1) * 128) + warp * 32 + ((mt & 1) * 16) + grp;

        // ============ layer 0 -> A1 ============
        u32 A1[4][4][4];
        {
            u32 Ag[4][2][4];
            const u32* AG = smu + O_ACTG;
            #pragma unroll
            for (int mt = 0; mt < 4; mt++) {
                int rA = mrow[mt], rB = rA + 8;
                #pragma unroll
                for (int k = 0; k < 2; k++) {
                    Ag[mt][k][0] = AG[agix(rA, k * 8 + tig)];
                    Ag[mt][k][1] = AG[agix(rB, k * 8 + tig)];
                    Ag[mt][k][2] = AG[agix(rA, k * 8 + 4 + tig)];
                    Ag[mt][k][3] = AG[agix(rB, k * 8 + 4 + tig)];
                }
            }
            const u32* WT = smu + O_W0GT;
            #pragma unroll
            for (int kg = 0; kg < 4; kg++) {
                float Ca[4][4], Cb[4][4];
                #pragma unroll
                for (int mt = 0; mt < 4; mt++) {
                    const float* bp = sm + O_BASE + (mt >> 1) * 64;
                    float v0 = bp[(2 * kg) * 8 + 2 * tig];
                    float v1 = bp[(2 * kg) * 8 + 2 * tig + 1];
                    Ca[mt][0] = v0; Ca[mt][1] = v1; Ca[mt][2] = v0; Ca[mt][3] = v1;
                    v0 = bp[(2 * kg + 1) * 8 + 2 * tig];
                    v1 = bp[(2 * kg + 1) * 8 + 2 * tig + 1];
                    Cb[mt][0] = v0; Cb[mt][1] = v1; Cb[mt][2] = v0; Cb[mt][3] = v1;
                }
                #pragma unroll
                for (int k = 0; k < 2; k++) {
                    u32 ba0 = WT[((2 * kg) * 8 + grp) * SW0G + k * 8 + tig];
                    u32 ba1 = WT[((2 * kg) * 8 + grp) * SW0G + k * 8 + 4 + tig];
                    u32 bb0 = WT[((2 * kg + 1) * 8 + grp) * SW0G + k * 8 + tig];
                    u32 bb1 = WT[((2 * kg + 1) * 8 + grp) * SW0G + k * 8 + 4 + tig];
                    #pragma unroll
                    for (int mt = 0; mt < 4; mt++) {
                        mma16(Ca[mt], Ag[mt][k], ba0, ba1);
                        mma16(Cb[mt], Ag[mt][k], bb0, bb1);
                    }
                }
                #pragma unroll
                for (int mt = 0; mt < 4; mt++) {
                    A1[mt][kg][0] = pkrelu(Ca[mt][0], Ca[mt][1]);
                    A1[mt][kg][1] = pkrelu(Ca[mt][2], Ca[mt][3]);
                    A1[mt][kg][2] = pkrelu(Cb[mt][0], Cb[mt][1]);
                    A1[mt][kg][3] = pkrelu(Cb[mt][2], Cb[mt][3]);
                }
            }
        }

        // ---- prefetch stage 2a: row a gathers ----
        if (pn) {
            float4 f0 = __ldg(gw + xva[0].x), f1 = __ldg(gw + xva[0].y);
            float4 f2 = __ldg(gw + xva[1].x), f3 = __ldg(gw + xva[1].y);
            float4 f4v = __ldg(gw + xva[2].x), f5 = __ldg(gw + xva[2].y);
            sgp[0] = fminf(fmaxf(f0.x, 0.f), 1.f) * fminf(fmaxf(f1.x, 0.f), 1.f)
                   * fminf(fmaxf(f2.x, 0.f), 1.f) * fminf(fmaxf(f3.x, 0.f), 1.f)
                   * fminf(fmaxf(f4v.x, 0.f), 1.f) * fminf(fmaxf(f5.x, 0.f), 1.f);
            gpk[0][0] = pkbf(f0.y, f0.z); gpk[0][1] = pkbf(f0.w, f1.y); gpk[0][2] = pkbf(f1.z, f1.w);
            gpk[0][3] = pkbf(f2.y, f2.z); gpk[0][4] = pkbf(f2.w, f3.y); gpk[0][5] = pkbf(f3.z, f3.w);
            gpk[0][6] = pkbf(f4v.y, f4v.z); gpk[0][7] = pkbf(f4v.w, f5.y); gpk[0][8] = pkbf(f5.z, f5.w);
        }

        // ============ layer 1 -> A2 ============
        u32 A2[4][4][4];
        {
            const u32* WT = smu + O_W1T;
            #pragma unroll
            for (int kg = 0; kg < 4; kg++) {
                float Ca[4][4], Cb[4][4];
                {
                    float v0 = sm[O_B1 + (2 * kg) * 8 + 2 * tig];
                    float v1 = sm[O_B1 + (2 * kg) * 8 + 2 * tig + 1];
                    float w0 = sm[O_B1 + (2 * kg + 1) * 8 + 2 * tig];
                    float w1 = sm[O_B1 + (2 * kg + 1) * 8 + 2 * tig + 1];
                    #pragma unroll
                    for (int mt = 0; mt < 4; mt++) {
                        Ca[mt][0] = v0; Ca[mt][1] = v1; Ca[mt][2] = v0; Ca[mt][3] = v1;
                        Cb[mt][0] = w0; Cb[mt][1] = w1; Cb[mt][2] = w0; Cb[mt][3] = w1;
                    }
                }
                #pragma unroll
                for (int k = 0; k < 4; k++) {
                    u32 ba0 = WT[((2 * kg) * 8 + grp) * SW1 + k * 8 + tig];
                    u32 ba1 = WT[((2 * kg) * 8 + grp) * SW1 + k * 8 + 4 + tig];
                    u32 bb0 = WT[((2 * kg + 1) * 8 + grp) * SW1 + k * 8 + tig];
                    u32 bb1 = WT[((2 * kg + 1) * 8 + grp) * SW1 + k * 8 + 4 + tig];
                    #pragma unroll
                    for (int mt = 0; mt < 4; mt++) {
                        mma16(Ca[mt], A1[mt][k], ba0, ba1);
                        mma16(Cb[mt], A1[mt][k], bb0, bb1);
                    }
                }
                #pragma unroll
                for (int mt = 0; mt < 4; mt++) {
                    A2[mt][kg][0] = pkrelu(Ca[mt][0], Ca[mt][1]);
                    A2[mt][kg][1] = pkrelu(Ca[mt][2], Ca[mt][3]);
                    A2[mt][kg][2] = pkrelu(Cb[mt][0], Cb[mt][1]);
                    A2[mt][kg][3] = pkrelu(Cb[mt][2], Cb[mt][3]);
                }
            }
        }

        // ---- prefetch stage 2b: row b gathers ----
        if (pn) {
            float4 f0 = __ldg(gw + xvb[0].x), f1 = __ldg(gw + xvb[0].y);
            float4 f2 = __ldg(gw + xvb[1].x), f3 = __ldg(gw + xvb[1].y);
            float4 f4v = __ldg(gw + xvb[2].x), f5 = __ldg(gw + xvb[2].y);
            sgp[1] = fminf(fmaxf(f0.x, 0.f), 1.f) * fminf(fmaxf(f1.x, 0.f), 1.f)
                   * fminf(fmaxf(f2.x, 0.f), 1.f) * fminf(fmaxf(f3.x, 0.f), 1.f)
                   * fminf(fmaxf(f4v.x, 0.f), 1.f) * fminf(fmaxf(f5.x, 0.f), 1.f);
            gpk[1][0] = pkbf(f0.y, f0.z); gpk[1][1] = pkbf(f0.w, f1.y); gpk[1][2] = pkbf(f1.z, f1.w);
            gpk[1][3] = pkbf(f2.y, f2.z); gpk[1][4] = pkbf(f2.w, f3.y); gpk[1][5] = pkbf(f3.z, f3.w);
            gpk[1][6] = pkbf(f4v.y, f4v.z); gpk[1][7] = pkbf(f4v.w, f5.y); gpk[1][8] = pkbf(f5.z, f5.w);
        }

        // ============ layer 2 -> logits ============
        {
            const u32* WT = smu + O_W2T;
            float bv0 = sm[O_B2 + 2 * tig];
            float bv1 = sm[O_B2 + 2 * tig + 1];
            float C[4][4];
            #pragma unroll
            for (int mt = 0; mt < 4; mt++) {
                C[mt][0] = bv0; C[mt][1] = bv1; C[mt][2] = bv0; C[mt][3] = bv1;
            }
            #pragma unroll
            for (int k = 0; k < 4; k++) {
                u32 bb0 = WT[grp * SW2 + k * 8 + tig];
                u32 bb1 = WT[grp * SW2 + k * 8 + 4 + tig];
                #pragma unroll
                for (int mt = 0; mt < 4; mt++)
                    mma16(C[mt], A2[mt][k], bb0, bb1);
            }
            #pragma unroll
            for (int mt = 0; mt < 4; mt++) {
                int rA = mrow[mt], rB = rA + 8;
                if (2 * tig < 3) {
                    sm[O_COLB + rA * SCB + 2 * tig] = C[mt][0];
                    sm[O_COLB + rB * SCB + 2 * tig] = C[mt][2];
                }
                if (2 * tig + 1 < 3) {
                    sm[O_COLB + rA * SCB + 2 * tig + 1] = C[mt][1];
                    sm[O_COLB + rB * SCB + 2 * tig + 1] = C[mt][3];
                }
            }
        }
        __syncwarp();   // COLB rows are warp-local; order stores before reads

        // ============ phase 3: sigmoid + weighted reductions (both rows) ============
        float l00 = sm[O_COLB + tid * SCB + 0];
        float l01 = sm[O_COLB + tid * SCB + 1];
        float l02 = sm[O_COLB + tid * SCB + 2];
        float l10 = sm[O_COLB + (128 + tid) * SCB + 0];
        float l11 = sm[O_COLB + (128 + tid) * SCB + 1];
        float l12 = sm[O_COLB + (128 + tid) * SCB + 2];
        float c00 = 1.0f / (1.0f + expf(-l00));
        float c01 = 1.0f / (1.0f + expf(-l01));
        float c02 = 1.0f / (1.0f + expf(-l02));
        float c10 = 1.0f / (1.0f + expf(-l10));
        float c11 = 1.0f / (1.0f + expf(-l11));
        float c12 = 1.0f / (1.0f + expf(-l12));
        float r0v = cw0 * c00, g0v = cw0 * c01, b0v = cw0 * c02;
        float r1v = cw1 * c10, g1v = cw1 * c11, b1v = cw1 * c12;
        #pragma unroll
        for (int o = 16; o; o >>= 1) {
            r0v += __shfl_xor_sync(0xffffffffu, r0v, o);
            g0v += __shfl_xor_sync(0xffffffffu, g0v, o);
            b0v += __shfl_xor_sync(0xffffffffu, b0v, o);
            r1v += __shfl_xor_sync(0xffffffffu, r1v, o);
            g1v += __shfl_xor_sync(0xffffffffu, g1v, o);
            b1v += __shfl_xor_sync(0xffffffffu, b1v, o);
        }
        if (lane == 0) {
            sm[O_COL + warp * 3 + 0] = r0v;
            sm[O_COL + warp * 3 + 1] = g0v;
            sm[O_COL + warp * 3 + 2] = b0v;
            sm[O_COL + 12 + warp * 3 + 0] = r1v;
            sm[O_COL + 12 + warp * 3 + 1] = g1v;
            sm[O_COL + 12 + warp * 3 + 2] = b1v;
        }
        __syncthreads();   // (C) publishes COL; gates next-iter smem writes
        if (tid < 6) {
            const int s = tid / 3, c = tid % 3;
            const float* cp = sm + O_COL + s * 12;
            outColor[(size_t)(2 * p + s) * 3 + c] = cp[c] + cp[3 + c] + cp[6 + c] + cp[9 + c];
        }
        p = np;
    }
}

extern "C" void kernel_launch(void* const* d_in, const int* in_sizes, int n_in,
                              void* d_out, int out_size)
{
    const int*    x  = (const int*)d_in[0];
    const float*  dv = (const float*)d_in[1];
    const float4* gw = (const float4*)d_in[2];
    const float*  W0 = (const float*)d_in[3];
    const float*  b0 = (const float*)d_in[4];
    const float*  W1 = (const float*)d_in[5];
    const float*  b1 = (const float*)d_in[6];
    const float*  W2 = (const float*)d_in[7];
    const float*  b2 = (const float*)d_in[8];

    const int B = in_sizes[0] / (BN * LVL);   // 16384
    float* outSigma = (float*)d_out;
    float* outColor = (float*)d_out + (size_t)B * BN;

    cudaFuncSetAttribute(surf_pair,
                         cudaFuncAttributeMaxDynamicSharedMemorySize, SMEM_BYTES);

    const int pairs = B >> 1;
    int grid = pairs < 296 ? pairs : 296;   // 2 blocks/SM persistent
    surf_pair<<<grid, 128, SMEM_BYTES>>>(x, dv, gw, W0, b0, W1, b1, W2, b2,
                                         outSigma, outColor, B);
}

// round 13
// speedup vs baseline: 1.0862x; 1.0862x over previous
#include <cuda_runtime.h>
#include <cuda_bf16.h>
#include <math.h>

// SurfNetwork v11 (resubmit after infra failure): v6 register-resident mma.sync
// MLP + two-deep prefetch. At row r's phase-1 we issue: gathers for r+1 (x was
// fetched a full iteration ago), x for r+2, d for r+1 -> every memory op gets
// >= one full iteration (~2500 cyc) of overlap. Packed gpk prefetch + per-warp
// shuffle base keep regs ~150 -> 3 blocks/SM.

#define BN   128
#define LVL  6
#define DIRD 16
#define GEO  18

#define SW0G 20
#define SW1  36
#define SW2  36
#define SAG  20
#define SCB  9

typedef unsigned int u32;

#define O_W0GT 0        // 64*20
#define O_W1T  1280     // 64*36
#define O_W2T  3584     // 8*36
#define O_W0D  3872     // 16*64 fp32
#define O_B0   4896     // 64
#define O_B1   4960     // 64
#define O_B2   5024     // 8
#define O_BASEW 5032    // 4*64 (warp-private base)
#define O_SIG  5288     // 128
#define O_MAX  5416     // 4
#define O_COL  5420     // 12
#define O_ACTG 5432     // 128*20
#define O_COLB 7992     // 128*9
#define SMEM_WORDS 9144
#define SMEM_BYTES (SMEM_WORDS * 4)   // 36576

__device__ __forceinline__ u32 pkbf(float lo, float hi) {
    u32 r; asm("cvt.rn.bf16x2.f32 %0, %1, %2;" : "=r"(r) : "f"(hi), "f"(lo));
    return r;
}
__device__ __forceinline__ u32 pkrelu(float lo, float hi) {
    return pkbf(fmaxf(lo, 0.0f), fmaxf(hi, 0.0f));
}
__device__ __forceinline__ void mma16(float* c, const u32* a, u32 b0, u32 b1) {
    asm volatile(
        "mma.sync.aligned.m16n8k16.row.col.f32.bf16.bf16.f32 "
        "{%0,%1,%2,%3},{%4,%5,%6,%7},{%8,%9},{%0,%1,%2,%3};"
        : "+f"(c[0]), "+f"(c[1]), "+f"(c[2]), "+f"(c[3])
        : "r"(a[0]), "r"(a[1]), "r"(a[2]), "r"(a[3]), "r"(b0), "r"(b1));
}
__device__ __forceinline__ int agix(int row, int j) {
    return row * SAG + (j ^ ((row >> 3) & 3));
}

__global__ void __launch_bounds__(128, 3)
surf_deep(const int* __restrict__ x,
          const float* __restrict__ dvec,
          const float4* __restrict__ gw,
          const float* __restrict__ W0, const float* __restrict__ b0,
          const float* __restrict__ W1, const float* __restrict__ b1,
          const float* __restrict__ W2, const float* __restrict__ b2,
          float* __restrict__ outSigma, float* __restrict__ outColor,
          int B)
{
    extern __shared__ float sm[];
    u32* smu = (u32*)sm;
    const int tid  = threadIdx.x;
    const int lane = tid & 31;
    const int warp = tid >> 5;
    const int grp  = lane >> 2;
    const int tig  = lane & 3;

    // ---------- stage weights (transposed, bf16x2) ----------
    for (int i = tid; i < 64 * SW0G; i += 128) {
        int n = i / SW0G, kk = i - n * SW0G;
        u32 v = 0;
        if (kk < 16) {
            int g0 = 2 * kk, g1 = 2 * kk + 1;
            float lo = (g0 < GEO) ? W0[(DIRD + g0) * 64 + n] : 0.0f;
            float hi = (g1 < GEO) ? W0[(DIRD + g1) * 64 + n] : 0.0f;
            v = pkbf(lo, hi);
        }
        smu[O_W0GT + i] = v;
    }
    for (int i = tid; i < 64 * SW1; i += 128) {
        int n = i / SW1, kk = i - n * SW1;
        u32 v = 0;
        if (kk < 32) v = pkbf(W1[(2 * kk) * 64 + n], W1[(2 * kk + 1) * 64 + n]);
        smu[O_W1T + i] = v;
    }
    for (int i = tid; i < 8 * SW2; i += 128) {
        int n = i / SW2, kk = i - n * SW2;
        u32 v = 0;
        if (kk < 32 && n < 3) v = pkbf(W2[(2 * kk) * 3 + n], W2[(2 * kk + 1) * 3 + n]);
        smu[O_W2T + i] = v;
    }
    for (int i = tid; i < DIRD * 64; i += 128) sm[O_W0D + i] = W0[i];
    if (tid < 64) { sm[O_B0 + tid] = b0[tid]; sm[O_B1 + tid] = b1[tid]; }
    if (tid < 8)  sm[O_B2 + tid] = (tid < 3) ? b2[tid] : 0.0f;
    for (int j = 9; j < 16; j++) smu[O_ACTG + agix(tid, j)] = 0;
    __syncthreads();

    const int gstride = gridDim.x;
    int row = blockIdx.x;

    // ---------- prologue: gathers for row, x for row+gs, d for row ----------
    u32   gpk[9];
    float sgpre, dpre;
    int2  xv0, xv1, xv2;
    xv0 = make_int2(0, 0); xv1 = xv0; xv2 = xv0;
    {
        const int2* xp2 = (const int2*)(x + ((size_t)row * BN + tid) * LVL);
        int2 a0 = __ldg(xp2), a1 = __ldg(xp2 + 1), a2 = __ldg(xp2 + 2);
        dpre = (lane < DIRD) ? __ldg(dvec + (size_t)row * DIRD + lane) : 0.0f;
        float4 f0 = __ldg(gw + a0.x), f1 = __ldg(gw + a0.y);
        float4 f2 = __ldg(gw + a1.x), f3 = __ldg(gw + a1.y);
        float4 f4v = __ldg(gw + a2.x), f5 = __ldg(gw + a2.y);
        sgpre = fminf(fmaxf(f0.x, 0.f), 1.f) * fminf(fmaxf(f1.x, 0.f), 1.f)
              * fminf(fmaxf(f2.x, 0.f), 1.f) * fminf(fmaxf(f3.x, 0.f), 1.f)
              * fminf(fmaxf(f4v.x, 0.f), 1.f) * fminf(fmaxf(f5.x, 0.f), 1.f);
        gpk[0] = pkbf(f0.y, f0.z); gpk[1] = pkbf(f0.w, f1.y); gpk[2] = pkbf(f1.z, f1.w);
        gpk[3] = pkbf(f2.y, f2.z); gpk[4] = pkbf(f2.w, f3.y); gpk[5] = pkbf(f3.z, f3.w);
        gpk[6] = pkbf(f4v.y, f4v.z); gpk[7] = pkbf(f4v.w, f5.y); gpk[8] = pkbf(f5.z, f5.w);
        if (row + gstride < B) {
            const int2* xn = (const int2*)(x + ((size_t)(row + gstride) * BN + tid) * LVL);
            xv0 = __ldg(xn); xv1 = __ldg(xn + 1); xv2 = __ldg(xn + 2);
        }
    }

    while (row < B) {
        const int nrow = row + gstride;
        const bool pn = nrow < B;

        // ===== phase 1: consume gpk/sgpre/dpre for this row =====
        float sg = sgpre + 1e-4f;
        sm[O_SIG + tid] = sg;
        #pragma unroll
        for (int j = 0; j < 9; j++) smu[O_ACTG + agix(tid, j)] = gpk[j];

        {   // per-warp base = b0 + d . W0dir (2 outputs/lane)
            const float2* b02 = (const float2*)(sm + O_B0);
            const float2* w0d2 = (const float2*)(sm + O_W0D);
            float2 acc = b02[lane];
            #pragma unroll
            for (int i = 0; i < DIRD; i++) {
                float di = __shfl_sync(0xffffffffu, dpre, i);
                float2 w = w0d2[i * 32 + lane];
                acc.x = fmaf(di, w.x, acc.x);
                acc.y = fmaf(di, w.y, acc.y);
            }
            ((float2*)(sm + O_BASEW + warp * 64))[lane] = acc;
        }
        {   // warp max
            float m = sg;
            #pragma unroll
            for (int o = 16; o; o >>= 1) m = fmaxf(m, __shfl_xor_sync(0xffffffffu, m, o));
            if (lane == 0) sm[O_MAX + warp] = m;
        }

        // ===== step 2: issue ALL next-row memory (full-iteration overlap) =====
        if (pn) {
            // gathers for nrow from xv (x fetched a full iteration ago)
            float4 f0 = __ldg(gw + xv0.x), f1 = __ldg(gw + xv0.y);
            float4 f2 = __ldg(gw + xv1.x), f3 = __ldg(gw + xv1.y);
            float4 f4v = __ldg(gw + xv2.x), f5 = __ldg(gw + xv2.y);
            sgpre = fminf(fmaxf(f0.x, 0.f), 1.f) * fminf(fmaxf(f1.x, 0.f), 1.f)
                  * fminf(fmaxf(f2.x, 0.f), 1.f) * fminf(fmaxf(f3.x, 0.f), 1.f)
                  * fminf(fmaxf(f4v.x, 0.f), 1.f) * fminf(fmaxf(f5.x, 0.f), 1.f);
            gpk[0] = pkbf(f0.y, f0.z); gpk[1] = pkbf(f0.w, f1.y); gpk[2] = pkbf(f1.z, f1.w);
            gpk[3] = pkbf(f2.y, f2.z); gpk[4] = pkbf(f2.w, f3.y); gpk[5] = pkbf(f3.z, f3.w);
            gpk[6] = pkbf(f4v.y, f4v.z); gpk[7] = pkbf(f4v.w, f5.y); gpk[8] = pkbf(f5.z, f5.w);
            // x for nrow+gs, d for nrow
            if (nrow + gstride < B) {
                const int2* xn = (const int2*)(x + ((size_t)(nrow + gstride) * BN + tid) * LVL);
                xv0 = __ldg(xn); xv1 = __ldg(xn + 1); xv2 = __ldg(xn + 2);
            }
            dpre = (lane < DIRD) ? __ldg(dvec + (size_t)nrow * DIRD + lane) : 0.0f;
        }

        __syncthreads();   // (A) publishes ActG/SIG/MAX/BASEW

        float m = fmaxf(fmaxf(sm[O_MAX + 0], sm[O_MAX + 1]), fmaxf(sm[O_MAX + 2], sm[O_MAX + 3]));
        float sigma = sg / m;
        outSigma[(size_t)row * BN + tid] = sigma;
        float tb = tid ? 1.0f - sm[O_SIG + tid - 1] / m : 1.0f;
        float cw = tb * sigma;

        const int r0 = warp * 32 + grp;
        const float* baseW = sm + O_BASEW + warp * 64;

        // ============ layer 0 -> A1 ============
        u32 A1[2][4][4];
        {
            u32 Ag[2][2][4];
            const u32* AG = smu + O_ACTG;
            #pragma unroll
            for (int mt = 0; mt < 2; mt++) {
                int rA = r0 + mt * 16, rB = rA + 8;
                #pragma unroll
                for (int k = 0; k < 2; k++) {
                    Ag[mt][k][0] = AG[agix(rA, k * 8 + tig)];
                    Ag[mt][k][1] = AG[agix(rB, k * 8 + tig)];
                    Ag[mt][k][2] = AG[agix(rA, k * 8 + 4 + tig)];
                    Ag[mt][k][3] = AG[agix(rB, k * 8 + 4 + tig)];
                }
            }
            const u32* WT = smu + O_W0GT;
            #pragma unroll
            for (int kg = 0; kg < 4; kg++) {
                float Ca[2][4], Cb[2][4];
                #pragma unroll
                for (int mt = 0; mt < 2; mt++) {
                    float v0 = baseW[(2 * kg) * 8 + 2 * tig];
                    float v1 = baseW[(2 * kg) * 8 + 2 * tig + 1];
                    Ca[mt][0] = v0; Ca[mt][1] = v1; Ca[mt][2] = v0; Ca[mt][3] = v1;
                    v0 = baseW[(2 * kg + 1) * 8 + 2 * tig];
                    v1 = baseW[(2 * kg + 1) * 8 + 2 * tig + 1];
                    Cb[mt][0] = v0; Cb[mt][1] = v1; Cb[mt][2] = v0; Cb[mt][3] = v1;
                }
                #pragma unroll
                for (int k = 0; k < 2; k++) {
                    u32 ba0 = WT[((2 * kg) * 8 + grp) * SW0G + k * 8 + tig];
                    u32 ba1 = WT[((2 * kg) * 8 + grp) * SW0G + k * 8 + 4 + tig];
                    u32 bb0 = WT[((2 * kg + 1) * 8 + grp) * SW0G + k * 8 + tig];
                    u32 bb1 = WT[((2 * kg + 1) * 8 + grp) * SW0G + k * 8 + 4 + tig];
                    #pragma unroll
                    for (int mt = 0; mt < 2; mt++) {
                        mma16(Ca[mt], Ag[mt][k], ba0, ba1);
                        mma16(Cb[mt], Ag[mt][k], bb0, bb1);
                    }
                }
                #pragma unroll
                for (int mt = 0; mt < 2; mt++) {
                    A1[mt][kg][0] = pkrelu(Ca[mt][0], Ca[mt][1]);
                    A1[mt][kg][1] = pkrelu(Ca[mt][2], Ca[mt][3]);
                    A1[mt][kg][2] = pkrelu(Cb[mt][0], Cb[mt][1]);
                    A1[mt][kg][3] = pkrelu(Cb[mt][2], Cb[mt][3]);
                }
            }
        }

        // ============ layer 1 -> A2 ============
        u32 A2[2][4][4];
        {
            const u32* WT = smu + O_W1T;
            #pragma unroll
            for (int kg = 0; kg < 4; kg++) {
                float Ca[2][4], Cb[2][4];
                #pragma unroll
                for (int mt = 0; mt < 2; mt++) {
                    float v0 = sm[O_B1 + (2 * kg) * 8 + 2 * tig];
                    float v1 = sm[O_B1 + (2 * kg) * 8 + 2 * tig + 1];
                    Ca[mt][0] = v0; Ca[mt][1] = v1; Ca[mt][2] = v0; Ca[mt][3] = v1;
                    v0 = sm[O_B1 + (2 * kg + 1) * 8 + 2 * tig];
                    v1 = sm[O_B1 + (2 * kg + 1) * 8 + 2 * tig + 1];
                    Cb[mt][0] = v0; Cb[mt][1] = v1; Cb[mt][2] = v0; Cb[mt][3] = v1;
                }
                #pragma unroll
                for (int k = 0; k < 4; k++) {
                    u32 ba0 = WT[((2 * kg) * 8 + grp) * SW1 + k * 8 + tig];
                    u32 ba1 = WT[((2 * kg) * 8 + grp) * SW1 + k * 8 + 4 + tig];
                    u32 bb0 = WT[((2 * kg + 1) * 8 + grp) * SW1 + k * 8 + tig];
                    u32 bb1 = WT[((2 * kg + 1) * 8 + grp) * SW1 + k * 8 + 4 + tig];
                    #pragma unroll
                    for (int mt = 0; mt < 2; mt++) {
                        mma16(Ca[mt], A1[mt][k], ba0, ba1);
                        mma16(Cb[mt], A1[mt][k], bb0, bb1);
                    }
                }
                #pragma unroll
                for (int mt = 0; mt < 2; mt++) {
                    A2[mt][kg][0] = pkrelu(Ca[mt][0], Ca[mt][1]);
                    A2[mt][kg][1] = pkrelu(Ca[mt][2], Ca[mt][3]);
                    A2[mt][kg][2] = pkrelu(Cb[mt][0], Cb[mt][1]);
                    A2[mt][kg][3] = pkrelu(Cb[mt][2], Cb[mt][3]);
                }
            }
        }

        // ============ layer 2 -> logits ============
        {
            const u32* WT = smu + O_W2T;
            float bv0 = sm[O_B2 + 2 * tig];
            float bv1 = sm[O_B2 + 2 * tig + 1];
            float C0[4] = {bv0, bv1, bv0, bv1};
            float C1[4] = {bv0, bv1, bv0, bv1};
            #pragma unroll
            for (int k = 0; k < 4; k++) {
                u32 bb0 = WT[grp * SW2 + k * 8 + tig];
                u32 bb1 = WT[grp * SW2 + k * 8 + 4 + tig];
                mma16(C0, A2[0][k], bb0, bb1);
                mma16(C1, A2[1][k], bb0, bb1);
            }
            const int r1 = r0 + 16;
            if (2 * tig < 3) {
                sm[O_COLB + r0 * SCB + 2 * tig]        = C0[0];
                sm[O_COLB + (r0 + 8) * SCB + 2 * tig]  = C0[2];
                sm[O_COLB + r1 * SCB + 2 * tig]        = C1[0];
                sm[O_COLB + (r1 + 8) * SCB + 2 * tig]  = C1[2];
            }
            if (2 * tig + 1 < 3) {
                sm[O_COLB + r0 * SCB + 2 * tig + 1]       = C0[1];
                sm[O_COLB + (r0 + 8) * SCB + 2 * tig + 1] = C0[3];
                sm[O_COLB + r1 * SCB + 2 * tig + 1]       = C1[1];
                sm[O_COLB + (r1 + 8) * SCB + 2 * tig + 1] = C1[3];
            }
        }
        __syncwarp();

        // ============ phase 3 ============
        float l0 = sm[O_COLB + tid * SCB + 0];
        float l1 = sm[O_COLB + tid * SCB + 1];
        float l2 = sm[O_COLB + tid * SCB + 2];
        float c0 = 1.0f / (1.0f + expf(-l0));
        float c1 = 1.0f / (1.0f + expf(-l1));
        float c2 = 1.0f / (1.0f + expf(-l2));
        float rr = cw * c0, gg = cw * c1, bb = cw * c2;
        #pragma unroll
        for (int o = 16; o; o >>= 1) {
            rr += __shfl_xor_sync(0xffffffffu, rr, o);
            gg += __shfl_xor_sync(0xffffffffu, gg, o);
            bb += __shfl_xor_sync(0xffffffffu, bb, o);
        }
        if (lane == 0) {
            sm[O_COL + warp * 3 + 0] = rr;
            sm[O_COL + warp * 3 + 1] = gg;
            sm[O_COL + warp * 3 + 2] = bb;
        }
        __syncthreads();   // (C)
        if (tid < 3) {
            outColor[(size_t)row * 3 + tid] =
                sm[O_COL + tid] + sm[O_COL + 3 + tid] +
                sm[O_COL + 6 + tid] + sm[O_COL + 9 + tid];
        }
        row = nrow;
    }
}

extern "C" void kernel_launch(void* const* d_in, const int* in_sizes, int n_in,
                              void* d_out, int out_size)
{
    const int*    x  = (const int*)d_in[0];
    const float*  dv = (const float*)d_in[1];
    const float4* gw = (const float4*)d_in[2];
    const float*  W0 = (const float*)d_in[3];
    const float*  b0 = (const float*)d_in[4];
    const float*  W1 = (const float*)d_in[5];
    const float*  b1 = (const float*)d_in[6];
    const float*  W2 = (const float*)d_in[7];
    const float*  b2 = (const float*)d_in[8];

    const int B = in_sizes[0] / (BN * LVL);   // 16384
    float* outSigma = (float*)d_out;
    float* outColor = (float*)d_out + (size_t)B * BN;

    cudaFuncSetAttribute(surf_deep,
                         cudaFuncAttributeMaxDynamicSharedMemorySize, SMEM_BYTES);

    int grid = B < 444 ? B : 444;   // 3 blocks/SM persistent
    surf_deep<<<grid, 128, SMEM_BYTES>>>(x, dv, gw, W0, b0, W1, b1, W2, b2,
                                         outSigma, outColor, B);
}